// round 11
// baseline (speedup 1.0000x reference)
#include <cuda_runtime.h>

#define BB 4096
#define NN 8192
#define DD 512
#define RR 4

__device__ float g_nll[NN];

__device__ __forceinline__ const float4* row_ptr4(const float* zi, const float* zj, int r) {
    const float* p = (r < BB) ? (zi + (size_t)r * DD) : (zj + (size_t)(r - BB) * DD);
    return reinterpret_cast<const float4*>(p);
}

// Round-6 body (best known: ~10.6us): one warp per row, fused norms + 5 dots
// + NLL, 20 LDG.128 front-loaded. Plus griddepcontrol.launch_dependents so the
// PDL-attributed reduce kernel launches while this kernel is still running.
__global__ void __launch_bounds__(128) fused_kernel(const float* __restrict__ zi,
                                                    const float* __restrict__ zj,
                                                    const int* __restrict__ neg_idx) {
    // Allow the dependent (reduce) kernel to begin launching as soon as all
    // CTAs of this grid have started. Its griddepcontrol.wait still blocks
    // until our memory is visible, so this is purely latency hiding.
    asm volatile("griddepcontrol.launch_dependents;");

    int row  = (blockIdx.x * blockDim.x + threadIdx.x) >> 5;
    int lane = threadIdx.x & 31;
    if (row >= NN) return;

    const float4* pi = row_ptr4(zi, zj, row);
    float4 x[4];
#pragma unroll
    for (int k = 0; k < 4; k++) x[k] = pi[lane + 32 * k];

    int4 nv = *reinterpret_cast<const int4*>(neg_idx + row * RR);
    int part[5];
    part[0] = (row + BB) & (NN - 1);
    part[1] = nv.x + (nv.x >= row ? 1 : 0);
    part[2] = nv.y + (nv.y >= row ? 1 : 0);
    part[3] = nv.z + (nv.z >= row ? 1 : 0);
    part[4] = nv.w + (nv.w >= row ? 1 : 0);

    // Front-load all partner data: 20 independent LDG.128 in flight
    float4 y[5][4];
#pragma unroll
    for (int p = 0; p < 5; p++) {
        const float4* pj = row_ptr4(zi, zj, part[p]);
#pragma unroll
        for (int k = 0; k < 4; k++) y[p][k] = pj[lane + 32 * k];
    }

    float x2 = 0.0f;
#pragma unroll
    for (int k = 0; k < 4; k++)
        x2 += x[k].x * x[k].x + x[k].y * x[k].y + x[k].z * x[k].z + x[k].w * x[k].w;

    float dot[5], y2[5];
#pragma unroll
    for (int p = 0; p < 5; p++) {
        float d = 0.0f, n = 0.0f;
#pragma unroll
        for (int k = 0; k < 4; k++) {
            float4 a = x[k], b = y[p][k];
            d += a.x * b.x + a.y * b.y + a.z * b.z + a.w * b.w;
            n += b.x * b.x + b.y * b.y + b.z * b.z + b.w * b.w;
        }
        dot[p] = d;
        y2[p]  = n;
    }

#pragma unroll
    for (int o = 16; o; o >>= 1) {
        x2 += __shfl_xor_sync(0xFFFFFFFFu, x2, o);
#pragma unroll
        for (int p = 0; p < 5; p++) {
            dot[p] += __shfl_xor_sync(0xFFFFFFFFu, dot[p], o);
            y2[p]  += __shfl_xor_sync(0xFFFFFFFFu, y2[p], o);
        }
    }

    if (lane == 0) {
        const float invT = 1.0f / (0.5f + 1e-8f);
        float rnx = 1.0f / fmaxf(sqrtf(x2), 1e-8f);
        float l[5];
#pragma unroll
        for (int p = 0; p < 5; p++) {
            float rny = 1.0f / fmaxf(sqrtf(y2[p]), 1e-8f);
            l[p] = dot[p] * rnx * rny * invT;
        }
        float m = l[0];
#pragma unroll
        for (int p = 1; p < 5; p++) m = fmaxf(m, l[p]);
        float se = 0.0f;
#pragma unroll
        for (int p = 0; p < 5; p++) se += expf(l[p] - m);
        g_nll[row] = m + logf(se) - l[0];
    }
}

// Deterministic reduce of 8192 NLLs -> mean. PDL: launched programmatically
// while fused_kernel still runs; griddepcontrol.wait blocks until fused's
// writes are visible, then ~1us of real work.
__global__ void __launch_bounds__(1024) reduce_kernel(float* __restrict__ out) {
    asm volatile("griddepcontrol.wait;" ::: "memory");

    __shared__ float warp_sums[32];
    int tid = threadIdx.x;            // 1024 threads
    float s = 0.0f;
#pragma unroll
    for (int k = 0; k < NN / 1024; k++) s += g_nll[tid + k * 1024];
#pragma unroll
    for (int o = 16; o; o >>= 1) s += __shfl_xor_sync(0xFFFFFFFFu, s, o);
    if ((tid & 31) == 0) warp_sums[tid >> 5] = s;
    __syncthreads();
    if (tid < 32) {
        float t = warp_sums[tid];
#pragma unroll
        for (int o = 16; o; o >>= 1) t += __shfl_xor_sync(0xFFFFFFFFu, t, o);
        if (tid == 0) out[0] = t * (1.0f / (float)NN);
    }
}

extern "C" void kernel_launch(void* const* d_in, const int* in_sizes, int n_in,
                              void* d_out, int out_size) {
    const float* zi      = (const float*)d_in[0];
    const float* zj      = (const float*)d_in[1];
    const int*   neg_idx = (const int*)d_in[2];
    float* out = (float*)d_out;

    fused_kernel<<<NN / 4, 128>>>(zi, zj, neg_idx);

    // Reduce kernel with Programmatic Dependent Launch: overlaps its launch
    // with fused_kernel's execution; griddepcontrol.wait provides ordering.
    cudaLaunchConfig_t cfg = {};
    cfg.gridDim  = dim3(1, 1, 1);
    cfg.blockDim = dim3(1024, 1, 1);
    cfg.dynamicSmemBytes = 0;
    cfg.stream = 0;
    cudaLaunchAttribute attr[1];
    attr[0].id = cudaLaunchAttributeProgrammaticStreamSerialization;
    attr[0].val.programmaticStreamSerializationAllowed = 1;
    cfg.attrs = attr;
    cfg.numAttrs = 1;
    cudaLaunchKernelEx(&cfg, reduce_kernel, out);
}

// round 12
// speedup vs baseline: 1.2243x; 1.2243x over previous
#include <cuda_runtime.h>

#define BB 4096
#define NN 8192
#define DD 512
#define RR 4

__device__ float g_rnorm[NN];
__device__ float g_nll[NN];

__device__ __forceinline__ const float4* row_ptr4(const float* zi, const float* zj, int r) {
    const float* p = (r < BB) ? (zi + (size_t)r * DD) : (zj + (size_t)(r - BB) * DD);
    return reinterpret_cast<const float4*>(p);
}

// Kernel 1: per-row inverse norms. TWO rows per warp -> 8 independent
// LDG.128 per lane (R5 version had 4 -> DRAM-latency-bound at 2.3 TB/s).
__global__ void __launch_bounds__(128) norms_kernel(const float* __restrict__ zi,
                                                    const float* __restrict__ zj) {
    int warp = (blockIdx.x * blockDim.x + threadIdx.x) >> 5;
    int lane = threadIdx.x & 31;
    int r0   = warp * 2;               // rows r0, r0+1 (same source tensor: BB even)
    if (r0 >= NN) return;

    const float4* p0 = row_ptr4(zi, zj, r0);
    const float4* p1 = row_ptr4(zi, zj, r0 + 1);

    float4 a[4], b[4];
#pragma unroll
    for (int k = 0; k < 4; k++) a[k] = p0[lane + 32 * k];
#pragma unroll
    for (int k = 0; k < 4; k++) b[k] = p1[lane + 32 * k];

    float s0 = 0.0f, s1 = 0.0f;
#pragma unroll
    for (int k = 0; k < 4; k++) {
        s0 += a[k].x * a[k].x + a[k].y * a[k].y + a[k].z * a[k].z + a[k].w * a[k].w;
        s1 += b[k].x * b[k].x + b[k].y * b[k].y + b[k].z * b[k].z + b[k].w * b[k].w;
    }
#pragma unroll
    for (int o = 16; o; o >>= 1) {
        s0 += __shfl_xor_sync(0xFFFFFFFFu, s0, o);
        s1 += __shfl_xor_sync(0xFFFFFFFFu, s1, o);
    }
    if (lane == 0) {
        g_rnorm[r0]     = 1.0f / fmaxf(sqrtf(s0), 1e-8f);
        g_rnorm[r0 + 1] = 1.0f / fmaxf(sqrtf(s1), 1e-8f);
    }
}

// Kernel 2: per-row 5 dot products (1 positive + 4 negatives) + per-row NLL.
// One warp per row; row i held in registers, partners gathered (L2-resident).
// (Byte-identical to the round-5 version measured at 5.75us.)
__global__ void logits_kernel(const float* __restrict__ zi, const float* __restrict__ zj,
                              const int* __restrict__ neg_idx) {
    int row = (blockIdx.x * blockDim.x + threadIdx.x) >> 5;
    int lane = threadIdx.x & 31;
    if (row >= NN) return;

    const float4* pi = row_ptr4(zi, zj, row);
    float4 x[4];
#pragma unroll
    for (int k = 0; k < 4; k++) x[k] = pi[lane + 32 * k];

    int part[5];
    part[0] = (row + BB) & (NN - 1);
#pragma unroll
    for (int r = 0; r < RR; r++) {
        int v = neg_idx[row * RR + r];
        part[r + 1] = v + (v >= row ? 1 : 0);
    }

    float dots[5];
#pragma unroll
    for (int p = 0; p < 5; p++) {
        const float4* pj = row_ptr4(zi, zj, part[p]);
        float4 y0 = pj[lane];
        float4 y1 = pj[lane + 32];
        float4 y2 = pj[lane + 64];
        float4 y3 = pj[lane + 96];
        float acc = 0.0f;
        acc += x[0].x * y0.x + x[0].y * y0.y + x[0].z * y0.z + x[0].w * y0.w;
        acc += x[1].x * y1.x + x[1].y * y1.y + x[1].z * y1.z + x[1].w * y1.w;
        acc += x[2].x * y2.x + x[2].y * y2.y + x[2].z * y2.z + x[2].w * y2.w;
        acc += x[3].x * y3.x + x[3].y * y3.y + x[3].z * y3.z + x[3].w * y3.w;
        dots[p] = acc;
    }
#pragma unroll
    for (int p = 0; p < 5; p++) {
#pragma unroll
        for (int o = 16; o; o >>= 1) dots[p] += __shfl_xor_sync(0xFFFFFFFFu, dots[p], o);
    }

    if (lane == 0) {
        const float invT = 1.0f / (0.5f + 1e-8f);
        float si = g_rnorm[row];
        float l[5];
#pragma unroll
        for (int p = 0; p < 5; p++) l[p] = dots[p] * si * g_rnorm[part[p]] * invT;
        float m = l[0];
#pragma unroll
        for (int p = 1; p < 5; p++) m = fmaxf(m, l[p]);
        float se = 0.0f;
#pragma unroll
        for (int p = 0; p < 5; p++) se += expf(l[p] - m);
        g_nll[row] = m + logf(se) - l[0];
    }
}

// Kernel 3: deterministic reduce of 8192 NLLs -> mean, single block.
// (Byte-identical to the round-5 version.)
__global__ void reduce_kernel(float* __restrict__ out) {
    __shared__ float warp_sums[32];
    int tid = threadIdx.x;            // 1024 threads
    float s = 0.0f;
#pragma unroll
    for (int k = 0; k < NN / 1024; k++) s += g_nll[tid + k * 1024];
#pragma unroll
    for (int o = 16; o; o >>= 1) s += __shfl_xor_sync(0xFFFFFFFFu, s, o);
    if ((tid & 31) == 0) warp_sums[tid >> 5] = s;
    __syncthreads();
    if (tid < 32) {
        float t = warp_sums[tid];
#pragma unroll
        for (int o = 16; o; o >>= 1) t += __shfl_xor_sync(0xFFFFFFFFu, t, o);
        if (tid == 0) out[0] = t * (1.0f / (float)NN);
    }
}

extern "C" void kernel_launch(void* const* d_in, const int* in_sizes, int n_in,
                              void* d_out, int out_size) {
    const float* zi      = (const float*)d_in[0];
    const float* zj      = (const float*)d_in[1];
    const int*   neg_idx = (const int*)d_in[2];
    float* out = (float*)d_out;

    norms_kernel<<<NN / 8, 128>>>(zi, zj);          // 2 rows/warp, 4 warps/block
    logits_kernel<<<NN / 4, 128>>>(zi, zj, neg_idx);
    reduce_kernel<<<1, 1024>>>(out);
}

// round 13
// speedup vs baseline: 1.4116x; 1.1530x over previous
#include <cuda_runtime.h>
#include <cstdint>

#define BB 4096
#define NN 8192
#define DD 512
#define RR 4
#define NBLK (NN / 4)   // 2048 blocks, 4 warps = 4 rows per block

__device__ float g_partial[NBLK];
__device__ unsigned int g_ticket;   // zero-init at load; reset by block 0 each run

__device__ __forceinline__ const float* row_ptr(const float* zi, const float* zj, int r) {
    return (r < BB) ? (zi + (size_t)r * DD) : (zj + (size_t)(r - BB) * DD);
}

// Pinned vector load: volatile asm keeps issue order (all loads before any
// consumer) and forces live destination registers -> ptxas cannot serialize
// the gather front the way it did in rounds 7-11.
__device__ __forceinline__ void ldg4(float4& v, const float* p) {
    asm volatile("ld.global.nc.v4.f32 {%0,%1,%2,%3}, [%4];"
                 : "=f"(v.x), "=f"(v.y), "=f"(v.z), "=f"(v.w)
                 : "l"(p));
}

// Single kernel: one warp per row (fused norms + 5 dots + NLL), block partial,
// fire-and-forget release ticket, block 0 = designated deterministic reducer.
__global__ void __launch_bounds__(128) fused_kernel(const float* __restrict__ zi,
                                                    const float* __restrict__ zj,
                                                    const int* __restrict__ neg_idx,
                                                    float* __restrict__ out) {
    __shared__ float s_nll[4];
    __shared__ float s_ws[4];

    int warp = threadIdx.x >> 5;
    int lane = threadIdx.x & 31;
    int row  = blockIdx.x * 4 + warp;
    int col  = lane * 4;                 // float offset of this lane's first float4

    // ---- per-row work ----
    int4 nv = *reinterpret_cast<const int4*>(neg_idx + row * RR);
    int part[5];
    part[0] = (row + BB) & (NN - 1);
    part[1] = nv.x + (nv.x >= row ? 1 : 0);
    part[2] = nv.y + (nv.y >= row ? 1 : 0);
    part[3] = nv.z + (nv.z >= row ? 1 : 0);
    part[4] = nv.w + (nv.w >= row ? 1 : 0);

    // Own row: 4 pinned loads
    const float* px = row_ptr(zi, zj, row);
    float4 x[4];
#pragma unroll
    for (int k = 0; k < 4; k++) ldg4(x[k], px + col + k * 128);

    // All 5 partners: 20 pinned loads, issued back-to-back (MLP = 24/lane)
    float4 y[5][4];
#pragma unroll
    for (int p = 0; p < 5; p++) {
        const float* pj = row_ptr(zi, zj, part[p]);
#pragma unroll
        for (int k = 0; k < 4; k++) ldg4(y[p][k], pj + col + k * 128);
    }

    float x2 = 0.0f;
#pragma unroll
    for (int k = 0; k < 4; k++)
        x2 += x[k].x * x[k].x + x[k].y * x[k].y + x[k].z * x[k].z + x[k].w * x[k].w;

    float dot[5], y2[5];
#pragma unroll
    for (int p = 0; p < 5; p++) {
        float d = 0.0f, n = 0.0f;
#pragma unroll
        for (int k = 0; k < 4; k++) {
            float4 a = x[k], b = y[p][k];
            d += a.x * b.x + a.y * b.y + a.z * b.z + a.w * b.w;
            n += b.x * b.x + b.y * b.y + b.z * b.z + b.w * b.w;
        }
        dot[p] = d;
        y2[p]  = n;
    }

#pragma unroll
    for (int o = 16; o; o >>= 1) {
        x2 += __shfl_xor_sync(0xFFFFFFFFu, x2, o);
#pragma unroll
        for (int p = 0; p < 5; p++) {
            dot[p] += __shfl_xor_sync(0xFFFFFFFFu, dot[p], o);
            y2[p]  += __shfl_xor_sync(0xFFFFFFFFu, y2[p], o);
        }
    }

    if (lane == 0) {
        const float invT = 1.0f / (0.5f + 1e-8f);
        float rnx = 1.0f / fmaxf(sqrtf(x2), 1e-8f);
        float l[5];
#pragma unroll
        for (int p = 0; p < 5; p++) {
            float rny = 1.0f / fmaxf(sqrtf(y2[p]), 1e-8f);
            l[p] = dot[p] * rnx * rny * invT;
        }
        float m = l[0];
#pragma unroll
        for (int p = 1; p < 5; p++) m = fmaxf(m, l[p]);
        float se = 0.0f;
#pragma unroll
        for (int p = 0; p < 5; p++) se += expf(l[p] - m);
        s_nll[warp] = m + logf(se) - l[0];
    }
    __syncthreads();

    // ---- cheap tail: partial to L2, fire-and-forget release-add ----
    if (threadIdx.x == 0) {
        float partial = s_nll[0] + s_nll[1] + s_nll[2] + s_nll[3];
        asm volatile("st.global.cg.f32 [%0], %1;"
                     :: "l"(&g_partial[blockIdx.x]), "f"(partial) : "memory");
        asm volatile("red.release.gpu.global.add.u32 [%0], 1;"
                     :: "l"(&g_ticket) : "memory");
    }

    // ---- block 0 = designated reducer (deterministic, fixed order) ----
    if (blockIdx.x == 0) {
        if (threadIdx.x == 0) {
            unsigned int v;
            do {
                __nanosleep(64);
                asm volatile("ld.acquire.gpu.global.u32 %0, [%1];"
                             : "=r"(v) : "l"(&g_ticket));
            } while (v < (unsigned int)NBLK);
        }
        __syncthreads();

        float s = 0.0f;
#pragma unroll
        for (int k = 0; k < NBLK / 128; k++) {
            float v;
            asm volatile("ld.global.cg.f32 %0, [%1];"
                         : "=f"(v) : "l"(&g_partial[threadIdx.x + k * 128]));
            s += v;
        }
#pragma unroll
        for (int o = 16; o; o >>= 1) s += __shfl_xor_sync(0xFFFFFFFFu, s, o);
        if (lane == 0) s_ws[warp] = s;
        __syncthreads();
        if (threadIdx.x == 0) {
            float tot = s_ws[0] + s_ws[1] + s_ws[2] + s_ws[3];
            out[0] = tot * (1.0f / (float)NN);
            g_ticket = 0u;   // all blocks have arrived; safe reset for next replay
        }
    }
}

extern "C" void kernel_launch(void* const* d_in, const int* in_sizes, int n_in,
                              void* d_out, int out_size) {
    const float* zi      = (const float*)d_in[0];
    const float* zj      = (const float*)d_in[1];
    const int*   neg_idx = (const int*)d_in[2];
    float* out = (float*)d_out;

    fused_kernel<<<NBLK, 128>>>(zi, zj, neg_idx, out);
}